// round 13
// baseline (speedup 1.0000x reference)
#include <cuda_runtime.h>
#include <cuda_bf16.h>
#include <cstdint>
#include <math.h>

// Problem sizes (fixed by setup_inputs)
#define NS 512     // samples
#define AD 2048    // feature dim
#define CC 1000    // classes
#define CP 1024    // classes padded to N-tile multiple

// Output layout: loss(1) | y | new_ave | new_cov | new_amount
#define OFF_Y    1
#define OFF_AVE  (1 + NS*CC)
#define OFF_COV  (OFF_AVE + CC*AD)
#define OFF_AMT  (OFF_COV + CC*AD)

// ---------------------------------------------------------------- scratch
__device__ float g_t3[NS];
__device__ float g_isda[NS*CC];
__device__ __nv_bfloat16 g_fhi[NS*AD], g_flo[NS*AD];     // bf16 split of F
__device__ __nv_bfloat16 g_cvb[NS*AD], g_wcb[NS*AD];     // bf16 cv_n, -2*w_n*cv_n
__device__ __nv_bfloat16 g_whi[CP*AD], g_wlo[CP*AD], g_wsq[CP*AD]; // W split + W^2, padded

// ================================================================ PTX utils
__device__ __forceinline__ uint32_t smem_u32(const void* p) {
    uint32_t a;
    asm("{ .reg .u64 t; cvta.to.shared.u64 t, %1; cvt.u32.u64 %0, t; }" : "=r"(a) : "l"(p));
    return a;
}
#define SWZ(o) ((o) ^ (((o) >> 3) & 0x70))

__device__ __forceinline__ void cp16(uint32_t dst, const void* src) {
    asm volatile("cp.async.cg.shared.global [%0], [%1], 16;" :: "r"(dst), "l"(src) : "memory");
}
#define CP_COMMIT() asm volatile("cp.async.commit_group;" ::: "memory")
template <int N> __device__ __forceinline__ void cp_wait() {
    asm volatile("cp.async.wait_group %0;" :: "n"(N) : "memory");
}
__device__ __forceinline__ void ldsm_x4(uint32_t addr, uint32_t* r) {
    asm volatile("ldmatrix.sync.aligned.m8n8.x4.shared.b16 {%0,%1,%2,%3}, [%4];"
        : "=r"(r[0]), "=r"(r[1]), "=r"(r[2]), "=r"(r[3]) : "r"(addr));
}
__device__ __forceinline__ void mma_bf16(float* d, const uint32_t* a, const uint32_t* b) {
    asm volatile("mma.sync.aligned.m16n8k16.row.col.f32.bf16.bf16.f32 "
        "{%0,%1,%2,%3}, {%4,%5,%6,%7}, {%8,%9}, {%0,%1,%2,%3};"
        : "+f"(d[0]), "+f"(d[1]), "+f"(d[2]), "+f"(d[3])
        : "r"(a[0]), "r"(a[1]), "r"(a[2]), "r"(a[3]), "r"(b[0]), "r"(b[1]));
}

// ================================================================ k_front
// bx == 0:                       zero loss slot
// bx in [1, 1+NCONV):            F/W bf16 conversions
// bx in [1+NCONV, +CC):          class finalize -> d_out ave/cov/amount
// bx in [1+NCONV+CC, +NS):       per-sample gather (cv_n, -2 w_n cv_n, t3)
#define FCONV_ITEMS (NS*AD/4)          // 262144 float4
#define WCONV_ITEMS (CP*AD/4)          // 524288 float4
#define NCONV ((FCONV_ITEMS + WCONV_ITEMS) / 256)   // 3072
#define FRONT_BLOCKS (1 + NCONV + CC + NS)

// deterministic in-block compaction of {p : labels[p]==c} in index order
__device__ __forceinline__ int build_list(const int* slab, int c, int* list,
                                          int* warp_base, int t) {
    int lane = t & 31, w = t >> 5;
    int p0 = 2*t, p1 = 2*t + 1;
    bool m0 = (slab[p0] == c), m1 = (slab[p1] == c);
    unsigned b0 = __ballot_sync(0xffffffffu, m0);
    unsigned b1 = __ballot_sync(0xffffffffu, m1);
    unsigned lt = (1u << lane) - 1u;
    int below = __popc(b0 & lt) + __popc(b1 & lt);
    int wtot = __popc(b0) + __popc(b1);
    if (lane == 0) warp_base[w] = wtot;
    __syncthreads();
    if (t == 0) {
        int run = 0;
        #pragma unroll
        for (int x = 0; x < 8; x++) { int v = warp_base[x]; warp_base[x] = run; run += v; }
        warp_base[8] = run;
    }
    __syncthreads();
    int base = warp_base[w] + below;
    if (m0) list[base] = p0;
    if (m1) list[base + (m0 ? 1 : 0)] = p1;
    __syncthreads();
    return warp_base[8];
}

__device__ __forceinline__ void class_stats_list(
    const float* __restrict__ F, const int* __restrict__ list, int cnt,
    float inv, int v, float4& mean, float4& q)
{
    float4 s = make_float4(0.f, 0.f, 0.f, 0.f);
    for (int p = 0; p < cnt; p++) {
        const float4* fr = (const float4*)(F + (size_t)list[p] * AD);
        float4 x = fr[v];
        s.x += x.x; s.y += x.y; s.z += x.z; s.w += x.w;
    }
    mean = make_float4(s.x*inv, s.y*inv, s.z*inv, s.w*inv);
    q = make_float4(0.f, 0.f, 0.f, 0.f);
    for (int p = 0; p < cnt; p++) {
        const float4* fr = (const float4*)(F + (size_t)list[p] * AD);
        float4 x = fr[v];
        float dx = x.x-mean.x, dy = x.y-mean.y, dz = x.z-mean.z, dw = x.w-mean.w;
        q.x += dx*dx; q.y += dy*dy; q.z += dz*dz; q.w += dw*dw;
    }
}

__global__ __launch_bounds__(256) void k_front(
    const float* __restrict__ F, const float* __restrict__ W,
    const int* __restrict__ labels,
    const float* __restrict__ ave_in, const float* __restrict__ cov_in,
    const float* __restrict__ amt_in, float* __restrict__ d_out)
{
    int t = threadIdx.x;
    int bx = blockIdx.x;

    if (bx == 0) {
        if (t == 0) d_out[0] = 0.f;
        return;
    }
    bx -= 1;

    if (bx < NCONV) {
        int id = bx * 256 + t;
        if (id < FCONV_ITEMS) {
            float4 f = ((const float4*)F)[id];
            float hx = __bfloat162float(__float2bfloat16(f.x));
            float hy = __bfloat162float(__float2bfloat16(f.y));
            float hz = __bfloat162float(__float2bfloat16(f.z));
            float hw = __bfloat162float(__float2bfloat16(f.w));
            __nv_bfloat162* hi = (__nv_bfloat162*)g_fhi;
            __nv_bfloat162* lo = (__nv_bfloat162*)g_flo;
            hi[2*id+0] = __floats2bfloat162_rn(hx, hy);
            hi[2*id+1] = __floats2bfloat162_rn(hz, hw);
            lo[2*id+0] = __floats2bfloat162_rn(f.x - hx, f.y - hy);
            lo[2*id+1] = __floats2bfloat162_rn(f.z - hz, f.w - hw);
        } else {
            int v = id - FCONV_ITEMS;
            int row = (v*4) / AD;
            float4 f = (row < CC) ? ((const float4*)W)[v] : make_float4(0.f, 0.f, 0.f, 0.f);
            float hx = __bfloat162float(__float2bfloat16(f.x));
            float hy = __bfloat162float(__float2bfloat16(f.y));
            float hz = __bfloat162float(__float2bfloat16(f.z));
            float hw = __bfloat162float(__float2bfloat16(f.w));
            __nv_bfloat162* hi = (__nv_bfloat162*)g_whi;
            __nv_bfloat162* lo = (__nv_bfloat162*)g_wlo;
            __nv_bfloat162* sq = (__nv_bfloat162*)g_wsq;
            hi[2*v+0] = __floats2bfloat162_rn(hx, hy);
            hi[2*v+1] = __floats2bfloat162_rn(hz, hw);
            lo[2*v+0] = __floats2bfloat162_rn(f.x - hx, f.y - hy);
            lo[2*v+1] = __floats2bfloat162_rn(f.z - hz, f.w - hw);
            sq[2*v+0] = __floats2bfloat162_rn(f.x*f.x, f.y*f.y);
            sq[2*v+1] = __floats2bfloat162_rn(f.z*f.z, f.w*f.w);
        }
        return;
    }
    bx -= NCONV;

    // ---------------- stats blocks
    __shared__ int slab[NS];
    __shared__ int list[NS];
    __shared__ int wb[9];
    slab[t] = labels[t];
    slab[t + 256] = labels[t + 256];
    __syncthreads();

    bool is_fin = (bx < CC);
    int i_samp = -1, c;
    if (is_fin) c = bx;
    else { i_samp = bx - CC; c = slab[i_samp]; }

    int cnt = build_list(slab, c, list, wb, t);

    float fcnt = (float)cnt;
    float amt = amt_in[c];
    float dsum = fcnt + amt;
    float w = (dsum > 0.f) ? (fcnt / dsum) : 0.f;
    float omw = 1.f - w;
    size_t base = (size_t)c * AD;
    const float4* av4 = (const float4*)(ave_in + base);
    const float4* cv4 = (const float4*)(cov_in + base);

    if (is_fin) {
        if (t == 0) d_out[OFF_AMT + c] = amt + fcnt;
        if (cnt == 0) {
            #pragma unroll
            for (int h = 0; h < 2; h++) {
                int v = t + h*256;
                float4 a = av4[v];
                float4 cvv = cv4[v];
                long o = base + 4l*v;
                d_out[OFF_AVE + o + 0] = a.x; d_out[OFF_AVE + o + 1] = a.y;
                d_out[OFF_AVE + o + 2] = a.z; d_out[OFF_AVE + o + 3] = a.w;
                d_out[OFF_COV + o + 0] = cvv.x; d_out[OFF_COV + o + 1] = cvv.y;
                d_out[OFF_COV + o + 2] = cvv.z; d_out[OFF_COV + o + 3] = cvv.w;
            }
            return;
        }
        float inv = 1.f / fcnt;
        #pragma unroll
        for (int h = 0; h < 2; h++) {
            int v = t + h*256;
            float4 mean, q;
            class_stats_list(F, list, cnt, inv, v, mean, q);
            float4 a = av4[v];
            float4 c0 = cv4[v];
            float ww = w * omw;
            float d0 = a.x - mean.x, d1 = a.y - mean.y, d2 = a.z - mean.z, d3 = a.w - mean.w;
            long o = base + 4l*v;
            d_out[OFF_AVE + o + 0] = a.x*omw + mean.x*w;
            d_out[OFF_AVE + o + 1] = a.y*omw + mean.y*w;
            d_out[OFF_AVE + o + 2] = a.z*omw + mean.z*w;
            d_out[OFF_AVE + o + 3] = a.w*omw + mean.w*w;
            d_out[OFF_COV + o + 0] = c0.x*omw + q.x*inv*w + ww*d0*d0;
            d_out[OFF_COV + o + 1] = c0.y*omw + q.y*inv*w + ww*d1*d1;
            d_out[OFF_COV + o + 2] = c0.z*omw + q.z*inv*w + ww*d2*d2;
            d_out[OFF_COV + o + 3] = c0.w*omw + q.w*inv*w + ww*d3*d3;
        }
    } else {
        // gather for sample i_samp (cnt >= 1)
        __shared__ float sh[256];
        float inv = 1.f / fcnt;
        const float4* wr = (const float4*)(W + base);
        __nv_bfloat162* cvd = (__nv_bfloat162*)(g_cvb + (size_t)i_samp * AD);
        __nv_bfloat162* wcd = (__nv_bfloat162*)(g_wcb + (size_t)i_samp * AD);
        float acc = 0.f;
        #pragma unroll
        for (int h = 0; h < 2; h++) {
            int v = t + h*256;
            float4 mean, q;
            class_stats_list(F, list, cnt, inv, v, mean, q);
            float4 a = av4[v];
            float4 c0 = cv4[v];
            float ww = w * omw;
            float d0 = a.x - mean.x, d1 = a.y - mean.y, d2 = a.z - mean.z, d3 = a.w - mean.w;
            float4 nc;
            nc.x = c0.x*omw + q.x*inv*w + ww*d0*d0;
            nc.y = c0.y*omw + q.y*inv*w + ww*d1*d1;
            nc.z = c0.z*omw + q.z*inv*w + ww*d2*d2;
            nc.w = c0.w*omw + q.w*inv*w + ww*d3*d3;
            float4 wf = wr[v];
            cvd[2*v+0] = __floats2bfloat162_rn(nc.x, nc.y);
            cvd[2*v+1] = __floats2bfloat162_rn(nc.z, nc.w);
            wcd[2*v+0] = __floats2bfloat162_rn(-2.f*wf.x*nc.x, -2.f*wf.y*nc.y);
            wcd[2*v+1] = __floats2bfloat162_rn(-2.f*wf.z*nc.z, -2.f*wf.w*nc.w);
            acc += wf.x*wf.x*nc.x + wf.y*wf.y*nc.y + wf.z*wf.z*nc.z + wf.w*wf.w*nc.w;
        }
        sh[t] = acc;
        __syncthreads();
        for (int s = 128; s > 0; s >>= 1) {
            if (t < s) sh[t] += sh[t + s];
            __syncthreads();
        }
        if (t == 0) g_t3[i_samp] = sh[0];
    }
}

// ================================================================ HMMA GEMM
// CTA tile 128(M) x 64(N), K chunk 64, double buffered, 512 threads.
// 16 warps: 4(M) x 4(N); each warp 32x16 output (same warp tile as R6).
#define TM 128
#define TN 64
#define KC 64
#define KITERS (AD/KC)              // 32
#define A_MAT_BYTES (128*128)       // 16384 per A matrix per stage
#define B_MAT_BYTES (64*128)        // 8192 per B matrix per stage
#define STAGE_BYTES (4*A_MAT_BYTES + 3*B_MAT_BYTES)   // 90112
#define GEMM_SMEM (2*STAGE_BYTES)   // 180224

__device__ __forceinline__ void load_stage(uint32_t stg, int k0, int i0, int j0, int tid) {
    const __nv_bfloat16* As[4] = {g_fhi, g_flo, g_cvb, g_wcb};
    const __nv_bfloat16* Bs[3] = {g_whi, g_wlo, g_wsq};
    // A: 4 mats x 128 rows x 8 chunks = 4096; B: 3 x 64 x 8 = 1536; total 5632 = 512*11
    #pragma unroll
    for (int q = 0; q < 11; q++) {
        int id = tid + q*512;
        if (id < 4096) {
            int m = id >> 10;
            int idx = id & 1023;
            int r = idx >> 3, c = idx & 7;
            const __nv_bfloat16* src = As[m] + (size_t)(i0 + r)*AD + k0 + c*8;
            cp16(stg + m*A_MAT_BYTES + SWZ(r*128 + c*16), src);
        } else {
            int id2 = id - 4096;
            int m = id2 >> 9;
            int idx = id2 & 511;
            int r = idx >> 3, c = idx & 7;
            const __nv_bfloat16* src = Bs[m] + (size_t)(j0 + r)*AD + k0 + c*8;
            cp16(stg + 4*A_MAT_BYTES + m*B_MAT_BYTES + SWZ(r*128 + c*16), src);
        }
    }
}

__global__ __launch_bounds__(512, 1) void k_gemm_mma(
    const float* __restrict__ bias, const int* __restrict__ ratio_bits,
    float* __restrict__ d_out)
{
    extern __shared__ char smem[];
    uint32_t sb = smem_u32(smem);
    int tid = threadIdx.x, wid = tid >> 5, lane = tid & 31;
    int mw = wid & 3, nw = wid >> 2;               // 4 x 4 warp grid
    int i0 = blockIdx.y * TM, j0 = blockIdx.x * TN;

    float accY[2][2][4] = {};   // [mt][nt][frag]
    float accT[2][2][4] = {};

    uint32_t stg0 = sb, stg1 = sb + STAGE_BYTES;
    load_stage(stg0, 0,  i0, j0, tid); CP_COMMIT();
    load_stage(stg1, KC, i0, j0, tid); CP_COMMIT();

    for (int it = 0; it < KITERS; ++it) {
        uint32_t stg = (it & 1) ? stg1 : stg0;
        if (it == KITERS - 1) cp_wait<0>(); else cp_wait<1>();
        __syncthreads();

        #pragma unroll
        for (int ks = 0; ks < 4; ks++) {
            // A fragments: 4 matrices x 2 m-tiles (warp rows mw*32 .. mw*32+31)
            uint32_t a[4][2][4];
            int arow = mw*32 + (lane & 15);
            int akb  = ks*32 + ((lane >> 4) << 4);
            #pragma unroll
            for (int m = 0; m < 4; m++) {
                #pragma unroll
                for (int mt = 0; mt < 2; mt++) {
                    uint32_t addr = stg + m*A_MAT_BYTES + SWZ((arow + mt*16)*128 + akb);
                    ldsm_x4(addr, a[m][mt]);
                }
            }
            // B fragments: 3 matrices, 16 n-cols each
            uint32_t b[3][4];
            int brow = nw*16 + ((lane >> 4) << 3) + (lane & 7);
            int bkb  = ks*32 + (((lane >> 3) & 1) << 4);
            #pragma unroll
            for (int m = 0; m < 3; m++) {
                uint32_t addr = stg + 4*A_MAT_BYTES + m*B_MAT_BYTES + SWZ(brow*128 + bkb);
                ldsm_x4(addr, b[m]);
            }
            #pragma unroll
            for (int mt = 0; mt < 2; mt++) {
                #pragma unroll
                for (int nt = 0; nt < 2; nt++) {
                    const uint32_t* bw = &b[0][nt*2];
                    const uint32_t* bl = &b[1][nt*2];
                    const uint32_t* bs = &b[2][nt*2];
                    mma_bf16(accY[mt][nt], a[0][mt], bw);   // Fhi*Whi
                    mma_bf16(accY[mt][nt], a[0][mt], bl);   // Fhi*Wlo
                    mma_bf16(accY[mt][nt], a[1][mt], bw);   // Flo*Whi
                    mma_bf16(accT[mt][nt], a[2][mt], bs);   // cv*W^2   (t1)
                    mma_bf16(accT[mt][nt], a[3][mt], bw);   // -2wcv*W  (-2*t2)
                }
            }
        }
        __syncthreads();
        if (it + 2 < KITERS) {
            load_stage(stg, (it + 2)*KC, i0, j0, tid);
            CP_COMMIT();
        }
    }

    // epilogue: direct from registers
    int bits = *ratio_bits;
    float ratio = (bits & 0x7f800000) ? __int_as_float(bits) : (float)bits;
    #pragma unroll
    for (int mt = 0; mt < 2; mt++) {
        #pragma unroll
        for (int half = 0; half < 2; half++) {
            int i = i0 + mw*32 + mt*16 + (lane >> 2) + half*8;
            float t3v = g_t3[i];
            #pragma unroll
            for (int nt = 0; nt < 2; nt++) {
                #pragma unroll
                for (int c2 = 0; c2 < 2; c2++) {
                    int j = j0 + nw*16 + nt*8 + (lane & 3)*2 + c2;
                    if (j < CC) {
                        float yv = accY[mt][nt][half*2 + c2] + bias[j];
                        d_out[OFF_Y + (size_t)i*CC + j] = yv;
                        g_isda[(size_t)i*CC + j] =
                            yv + 0.5f * ratio * (accT[mt][nt][half*2 + c2] + t3v);
                    }
                }
            }
        }
    }
}

// ================================================================ loss
__global__ void k_loss(const int* __restrict__ labels, float* __restrict__ d_out) {
    __shared__ float sh[256];
    int i = blockIdx.x;
    const float* row = g_isda + (size_t)i * CC;
    float m = -INFINITY;
    for (int j = threadIdx.x; j < CC; j += 256) m = fmaxf(m, row[j]);
    sh[threadIdx.x] = m;
    __syncthreads();
    for (int s = 128; s > 0; s >>= 1) {
        if (threadIdx.x < s) sh[threadIdx.x] = fmaxf(sh[threadIdx.x], sh[threadIdx.x + s]);
        __syncthreads();
    }
    float mx = sh[0];
    __syncthreads();
    float acc = 0.f;
    for (int j = threadIdx.x; j < CC; j += 256) acc += __expf(row[j] - mx);
    sh[threadIdx.x] = acc;
    __syncthreads();
    for (int s = 128; s > 0; s >>= 1) {
        if (threadIdx.x < s) sh[threadIdx.x] += sh[threadIdx.x + s];
        __syncthreads();
    }
    if (threadIdx.x == 0) {
        float lp = row[labels[i]] - mx - logf(sh[0]);
        atomicAdd(d_out, -lp * (1.0f / (float)NS));
    }
}

// ================================================================ launcher
extern "C" void kernel_launch(void* const* d_in, const int* in_sizes, int n_in,
                              void* d_out, int out_size) {
    const float* features = (const float*)d_in[0];
    const int*   labels   = (const int*)  d_in[1];
    const float* fc_w     = (const float*)d_in[2];
    const float* fc_b     = (const float*)d_in[3];
    const float* ave_in   = (const float*)d_in[4];
    const float* cov_in   = (const float*)d_in[5];
    const float* amt_in   = (const float*)d_in[6];
    const int*   ratio_p  = (const int*)  d_in[7];
    float* out = (float*)d_out;

    cudaFuncSetAttribute(k_gemm_mma, cudaFuncAttributeMaxDynamicSharedMemorySize, GEMM_SMEM);

    k_front<<<FRONT_BLOCKS, 256>>>(features, fc_w, labels, ave_in, cov_in, amt_in, out);
    dim3 grid(CP / TN, NS / TM);          // 16 x 4 = 64 CTAs
    k_gemm_mma<<<grid, 512, GEMM_SMEM>>>(fc_b, ratio_p, out);
    k_loss<<<NS, 256>>>(labels, out);
}

// round 14
// speedup vs baseline: 1.5794x; 1.5794x over previous
#include <cuda_runtime.h>
#include <cuda_bf16.h>
#include <cstdint>
#include <math.h>

// Problem sizes (fixed by setup_inputs)
#define NS 512     // samples
#define AD 2048    // feature dim
#define CC 1000    // classes
#define CP 1024    // classes padded to N-tile multiple

// Output layout: loss(1) | y | new_ave | new_cov | new_amount
#define OFF_Y    1
#define OFF_AVE  (1 + NS*CC)
#define OFF_COV  (OFF_AVE + CC*AD)
#define OFF_AMT  (OFF_COV + CC*AD)

// ---------------------------------------------------------------- scratch
__device__ float g_t3[NS];
__device__ float g_isda[NS*CC];
__device__ __nv_bfloat16 g_fhi[NS*AD], g_flo[NS*AD];     // bf16 split of F
__device__ __nv_bfloat16 g_cvb[NS*AD], g_wcb[NS*AD];     // bf16 cv_n, -2*w_n*cv_n
__device__ __nv_bfloat16 g_whi[CP*AD], g_wlo[CP*AD], g_wsq[CP*AD]; // W split + W^2, padded

// ================================================================ PTX utils
__device__ __forceinline__ uint32_t smem_u32(const void* p) {
    uint32_t a;
    asm("{ .reg .u64 t; cvta.to.shared.u64 t, %1; cvt.u32.u64 %0, t; }" : "=r"(a) : "l"(p));
    return a;
}
#define SWZ(o) ((o) ^ (((o) >> 3) & 0x70))

__device__ __forceinline__ void cp16(uint32_t dst, const void* src) {
    asm volatile("cp.async.cg.shared.global [%0], [%1], 16;" :: "r"(dst), "l"(src) : "memory");
}
#define CP_COMMIT() asm volatile("cp.async.commit_group;" ::: "memory")
template <int N> __device__ __forceinline__ void cp_wait() {
    asm volatile("cp.async.wait_group %0;" :: "n"(N) : "memory");
}
__device__ __forceinline__ void ldsm_x4(uint32_t addr, uint32_t* r) {
    asm volatile("ldmatrix.sync.aligned.m8n8.x4.shared.b16 {%0,%1,%2,%3}, [%4];"
        : "=r"(r[0]), "=r"(r[1]), "=r"(r[2]), "=r"(r[3]) : "r"(addr));
}
__device__ __forceinline__ void mma_bf16(float* d, const uint32_t* a, const uint32_t* b) {
    asm volatile("mma.sync.aligned.m16n8k16.row.col.f32.bf16.bf16.f32 "
        "{%0,%1,%2,%3}, {%4,%5,%6,%7}, {%8,%9}, {%0,%1,%2,%3};"
        : "+f"(d[0]), "+f"(d[1]), "+f"(d[2]), "+f"(d[3])
        : "r"(a[0]), "r"(a[1]), "r"(a[2]), "r"(a[3]), "r"(b[0]), "r"(b[1]));
}

// ================================================================ k_front (exact R12)
#define FCONV_ITEMS (NS*AD/4)          // 262144 float4
#define WCONV_ITEMS (CP*AD/4)          // 524288 float4
#define NCONV ((FCONV_ITEMS + WCONV_ITEMS) / 256)   // 3072
#define FRONT_BLOCKS (1 + NCONV + CC + NS)

__device__ __forceinline__ int build_list(const int* slab, int c, int* list,
                                          int* warp_base, int t) {
    int lane = t & 31, w = t >> 5;
    int p0 = 2*t, p1 = 2*t + 1;
    bool m0 = (slab[p0] == c), m1 = (slab[p1] == c);
    unsigned b0 = __ballot_sync(0xffffffffu, m0);
    unsigned b1 = __ballot_sync(0xffffffffu, m1);
    unsigned lt = (1u << lane) - 1u;
    int below = __popc(b0 & lt) + __popc(b1 & lt);
    int wtot = __popc(b0) + __popc(b1);
    if (lane == 0) warp_base[w] = wtot;
    __syncthreads();
    if (t == 0) {
        int run = 0;
        #pragma unroll
        for (int x = 0; x < 8; x++) { int v = warp_base[x]; warp_base[x] = run; run += v; }
        warp_base[8] = run;
    }
    __syncthreads();
    int base = warp_base[w] + below;
    if (m0) list[base] = p0;
    if (m1) list[base + (m0 ? 1 : 0)] = p1;
    __syncthreads();
    return warp_base[8];
}

__device__ __forceinline__ void class_stats_list(
    const float* __restrict__ F, const int* __restrict__ list, int cnt,
    float inv, int v, float4& mean, float4& q)
{
    float4 s = make_float4(0.f, 0.f, 0.f, 0.f);
    for (int p = 0; p < cnt; p++) {
        const float4* fr = (const float4*)(F + (size_t)list[p] * AD);
        float4 x = fr[v];
        s.x += x.x; s.y += x.y; s.z += x.z; s.w += x.w;
    }
    mean = make_float4(s.x*inv, s.y*inv, s.z*inv, s.w*inv);
    q = make_float4(0.f, 0.f, 0.f, 0.f);
    for (int p = 0; p < cnt; p++) {
        const float4* fr = (const float4*)(F + (size_t)list[p] * AD);
        float4 x = fr[v];
        float dx = x.x-mean.x, dy = x.y-mean.y, dz = x.z-mean.z, dw = x.w-mean.w;
        q.x += dx*dx; q.y += dy*dy; q.z += dz*dz; q.w += dw*dw;
    }
}

__global__ __launch_bounds__(256) void k_front(
    const float* __restrict__ F, const float* __restrict__ W,
    const int* __restrict__ labels,
    const float* __restrict__ ave_in, const float* __restrict__ cov_in,
    const float* __restrict__ amt_in, float* __restrict__ d_out)
{
    int t = threadIdx.x;
    int bx = blockIdx.x;

    if (bx == 0) {
        if (t == 0) d_out[0] = 0.f;
        return;
    }
    bx -= 1;

    if (bx < NCONV) {
        int id = bx * 256 + t;
        if (id < FCONV_ITEMS) {
            float4 f = ((const float4*)F)[id];
            float hx = __bfloat162float(__float2bfloat16(f.x));
            float hy = __bfloat162float(__float2bfloat16(f.y));
            float hz = __bfloat162float(__float2bfloat16(f.z));
            float hw = __bfloat162float(__float2bfloat16(f.w));
            __nv_bfloat162* hi = (__nv_bfloat162*)g_fhi;
            __nv_bfloat162* lo = (__nv_bfloat162*)g_flo;
            hi[2*id+0] = __floats2bfloat162_rn(hx, hy);
            hi[2*id+1] = __floats2bfloat162_rn(hz, hw);
            lo[2*id+0] = __floats2bfloat162_rn(f.x - hx, f.y - hy);
            lo[2*id+1] = __floats2bfloat162_rn(f.z - hz, f.w - hw);
        } else {
            int v = id - FCONV_ITEMS;
            int row = (v*4) / AD;
            float4 f = (row < CC) ? ((const float4*)W)[v] : make_float4(0.f, 0.f, 0.f, 0.f);
            float hx = __bfloat162float(__float2bfloat16(f.x));
            float hy = __bfloat162float(__float2bfloat16(f.y));
            float hz = __bfloat162float(__float2bfloat16(f.z));
            float hw = __bfloat162float(__float2bfloat16(f.w));
            __nv_bfloat162* hi = (__nv_bfloat162*)g_whi;
            __nv_bfloat162* lo = (__nv_bfloat162*)g_wlo;
            __nv_bfloat162* sq = (__nv_bfloat162*)g_wsq;
            hi[2*v+0] = __floats2bfloat162_rn(hx, hy);
            hi[2*v+1] = __floats2bfloat162_rn(hz, hw);
            lo[2*v+0] = __floats2bfloat162_rn(f.x - hx, f.y - hy);
            lo[2*v+1] = __floats2bfloat162_rn(f.z - hz, f.w - hw);
            sq[2*v+0] = __floats2bfloat162_rn(f.x*f.x, f.y*f.y);
            sq[2*v+1] = __floats2bfloat162_rn(f.z*f.z, f.w*f.w);
        }
        return;
    }
    bx -= NCONV;

    __shared__ int slab[NS];
    __shared__ int list[NS];
    __shared__ int wb[9];
    slab[t] = labels[t];
    slab[t + 256] = labels[t + 256];
    __syncthreads();

    bool is_fin = (bx < CC);
    int i_samp = -1, c;
    if (is_fin) c = bx;
    else { i_samp = bx - CC; c = slab[i_samp]; }

    int cnt = build_list(slab, c, list, wb, t);

    float fcnt = (float)cnt;
    float amt = amt_in[c];
    float dsum = fcnt + amt;
    float w = (dsum > 0.f) ? (fcnt / dsum) : 0.f;
    float omw = 1.f - w;
    size_t base = (size_t)c * AD;
    const float4* av4 = (const float4*)(ave_in + base);
    const float4* cv4 = (const float4*)(cov_in + base);

    if (is_fin) {
        if (t == 0) d_out[OFF_AMT + c] = amt + fcnt;
        if (cnt == 0) {
            #pragma unroll
            for (int h = 0; h < 2; h++) {
                int v = t + h*256;
                float4 a = av4[v];
                float4 cvv = cv4[v];
                long o = base + 4l*v;
                d_out[OFF_AVE + o + 0] = a.x; d_out[OFF_AVE + o + 1] = a.y;
                d_out[OFF_AVE + o + 2] = a.z; d_out[OFF_AVE + o + 3] = a.w;
                d_out[OFF_COV + o + 0] = cvv.x; d_out[OFF_COV + o + 1] = cvv.y;
                d_out[OFF_COV + o + 2] = cvv.z; d_out[OFF_COV + o + 3] = cvv.w;
            }
            return;
        }
        float inv = 1.f / fcnt;
        #pragma unroll
        for (int h = 0; h < 2; h++) {
            int v = t + h*256;
            float4 mean, q;
            class_stats_list(F, list, cnt, inv, v, mean, q);
            float4 a = av4[v];
            float4 c0 = cv4[v];
            float ww = w * omw;
            float d0 = a.x - mean.x, d1 = a.y - mean.y, d2 = a.z - mean.z, d3 = a.w - mean.w;
            long o = base + 4l*v;
            d_out[OFF_AVE + o + 0] = a.x*omw + mean.x*w;
            d_out[OFF_AVE + o + 1] = a.y*omw + mean.y*w;
            d_out[OFF_AVE + o + 2] = a.z*omw + mean.z*w;
            d_out[OFF_AVE + o + 3] = a.w*omw + mean.w*w;
            d_out[OFF_COV + o + 0] = c0.x*omw + q.x*inv*w + ww*d0*d0;
            d_out[OFF_COV + o + 1] = c0.y*omw + q.y*inv*w + ww*d1*d1;
            d_out[OFF_COV + o + 2] = c0.z*omw + q.z*inv*w + ww*d2*d2;
            d_out[OFF_COV + o + 3] = c0.w*omw + q.w*inv*w + ww*d3*d3;
        }
    } else {
        __shared__ float sh[256];
        float inv = 1.f / fcnt;
        const float4* wr = (const float4*)(W + base);
        __nv_bfloat162* cvd = (__nv_bfloat162*)(g_cvb + (size_t)i_samp * AD);
        __nv_bfloat162* wcd = (__nv_bfloat162*)(g_wcb + (size_t)i_samp * AD);
        float acc = 0.f;
        #pragma unroll
        for (int h = 0; h < 2; h++) {
            int v = t + h*256;
            float4 mean, q;
            class_stats_list(F, list, cnt, inv, v, mean, q);
            float4 a = av4[v];
            float4 c0 = cv4[v];
            float ww = w * omw;
            float d0 = a.x - mean.x, d1 = a.y - mean.y, d2 = a.z - mean.z, d3 = a.w - mean.w;
            float4 nc;
            nc.x = c0.x*omw + q.x*inv*w + ww*d0*d0;
            nc.y = c0.y*omw + q.y*inv*w + ww*d1*d1;
            nc.z = c0.z*omw + q.z*inv*w + ww*d2*d2;
            nc.w = c0.w*omw + q.w*inv*w + ww*d3*d3;
            float4 wf = wr[v];
            cvd[2*v+0] = __floats2bfloat162_rn(nc.x, nc.y);
            cvd[2*v+1] = __floats2bfloat162_rn(nc.z, nc.w);
            wcd[2*v+0] = __floats2bfloat162_rn(-2.f*wf.x*nc.x, -2.f*wf.y*nc.y);
            wcd[2*v+1] = __floats2bfloat162_rn(-2.f*wf.z*nc.z, -2.f*wf.w*nc.w);
            acc += wf.x*wf.x*nc.x + wf.y*wf.y*nc.y + wf.z*wf.z*nc.z + wf.w*wf.w*nc.w;
        }
        sh[t] = acc;
        __syncthreads();
        for (int s = 128; s > 0; s >>= 1) {
            if (t < s) sh[t] += sh[t + s];
            __syncthreads();
        }
        if (t == 0) g_t3[i_samp] = sh[0];
    }
}

// ================================================================ HMMA GEMM
// CTA tile 64x64, 128 CTAs, 256 threads / 8 warps arranged 2M x 2N x 2Ksl.
// Each warp: 32x32 output quadrant for half the k-steps; cross-K merge via smem.
#define TM 64
#define TN 64
#define KC 64
#define KITERS (AD/KC)              // 32
#define MAT_BYTES (64*128)          // 8192 per matrix per stage
#define STAGE_BYTES (7*MAT_BYTES)   // 57344
#define GEMM_SMEM (2*STAGE_BYTES)   // 114688

__device__ __forceinline__ void load_stage(uint32_t stg, int k0, int i0, int j0, int tid) {
    const __nv_bfloat16* As[4] = {g_fhi, g_flo, g_cvb, g_wcb};
    const __nv_bfloat16* Bs[3] = {g_whi, g_wlo, g_wsq};
    #pragma unroll
    for (int q = 0; q < 14; q++) {
        int id = tid + q*256;
        int m = (id >> 9) & 7;
        int idx = id & 511;
        int r = idx >> 3, c = idx & 7;
        if (id < 2048) {
            const __nv_bfloat16* src = As[m] + (size_t)(i0 + r)*AD + k0 + c*8;
            cp16(stg + m*MAT_BYTES + SWZ(r*128 + c*16), src);
        } else {
            m = (id - 2048) >> 9;
            const __nv_bfloat16* src = Bs[m] + (size_t)(j0 + r)*AD + k0 + c*8;
            cp16(stg + (4+m)*MAT_BYTES + SWZ(r*128 + c*16), src);
        }
    }
}

__global__ __launch_bounds__(256, 1) void k_gemm_mma(
    const float* __restrict__ bias, const int* __restrict__ ratio_bits,
    float* __restrict__ d_out)
{
    extern __shared__ char smem[];
    uint32_t sb = smem_u32(smem);
    int tid = threadIdx.x, wid = tid >> 5, lane = tid & 31;
    int mw = wid & 1, nwp = (wid >> 1) & 1, kw = wid >> 2;   // 2M x 2N x 2Ksl
    int i0 = blockIdx.y * TM, j0 = blockIdx.x * TN;

    float accY[2][4][4] = {};   // [mt][bt*2+nt8][frag]
    float accT[2][4][4] = {};

    uint32_t stg0 = sb, stg1 = sb + STAGE_BYTES;
    load_stage(stg0, 0,  i0, j0, tid); CP_COMMIT();
    load_stage(stg1, KC, i0, j0, tid); CP_COMMIT();

    for (int it = 0; it < KITERS; ++it) {
        uint32_t stg = (it & 1) ? stg1 : stg0;
        if (it == KITERS - 1) cp_wait<0>(); else cp_wait<1>();
        __syncthreads();

        #pragma unroll
        for (int s = 0; s < 2; s++) {
            int ks = kw*2 + s;                 // this warp's k16 step
            // A fragments: 4 matrices x 2 m-tiles (warp rows mw*32..+31)
            uint32_t a[4][2][4];
            int arow = mw*32 + (lane & 15);
            int akb  = ks*32 + ((lane >> 4) << 4);
            #pragma unroll
            for (int m = 0; m < 4; m++) {
                #pragma unroll
                for (int mt = 0; mt < 2; mt++) {
                    uint32_t addr = stg + m*MAT_BYTES + SWZ((arow + mt*16)*128 + akb);
                    ldsm_x4(addr, a[m][mt]);
                }
            }
            // B fragments: 3 matrices x 2 n16-tiles (warp cols nwp*32..+31)
            uint32_t b[3][2][4];
            int bkb = ks*32 + (((lane >> 3) & 1) << 4);
            #pragma unroll
            for (int m = 0; m < 3; m++) {
                #pragma unroll
                for (int bt = 0; bt < 2; bt++) {
                    int brow = nwp*32 + bt*16 + ((lane >> 4) << 3) + (lane & 7);
                    uint32_t addr = stg + (4+m)*MAT_BYTES + SWZ(brow*128 + bkb);
                    ldsm_x4(addr, b[m][bt]);
                }
            }
            #pragma unroll
            for (int mt = 0; mt < 2; mt++) {
                #pragma unroll
                for (int bt = 0; bt < 2; bt++) {
                    #pragma unroll
                    for (int n8 = 0; n8 < 2; n8++) {
                        int q = bt*2 + n8;
                        const uint32_t* bw = &b[0][bt][n8*2];
                        const uint32_t* bl = &b[1][bt][n8*2];
                        const uint32_t* bs = &b[2][bt][n8*2];
                        mma_bf16(accY[mt][q], a[0][mt], bw);   // Fhi*Whi
                        mma_bf16(accY[mt][q], a[0][mt], bl);   // Fhi*Wlo
                        mma_bf16(accY[mt][q], a[1][mt], bw);   // Flo*Whi
                        mma_bf16(accT[mt][q], a[2][mt], bs);   // cv*W^2   (t1)
                        mma_bf16(accT[mt][q], a[3][mt], bw);   // -2wcv*W  (-2*t2)
                    }
                }
            }
        }
        __syncthreads();
        if (it + 2 < KITERS) {
            load_stage(stg, (it + 2)*KC, i0, j0, tid);
            CP_COMMIT();
        }
    }

    // ---- cross-K merge: kw=1 warps stash partials, kw=0 warps add
    __syncthreads();
    float* mY = (float*)smem;          // 64x64 f32 = 16 KB
    float* mT = mY + TM*TN;            // 16 KB
    if (kw == 1) {
        #pragma unroll
        for (int mt = 0; mt < 2; mt++) {
            #pragma unroll
            for (int q = 0; q < 4; q++) {
                #pragma unroll
                for (int f = 0; f < 4; f++) {
                    int rr = mw*32 + mt*16 + (lane >> 2) + ((f >> 1) << 3);
                    int cc = nwp*32 + (q >> 1)*16 + (q & 1)*8 + (lane & 3)*2 + (f & 1);
                    mY[rr*TN + cc] = accY[mt][q][f];
                    mT[rr*TN + cc] = accT[mt][q][f];
                }
            }
        }
    }
    __syncthreads();

    if (kw == 0) {
        int bits = *ratio_bits;
        float ratio = (bits & 0x7f800000) ? __int_as_float(bits) : (float)bits;
        #pragma unroll
        for (int mt = 0; mt < 2; mt++) {
            #pragma unroll
            for (int q = 0; q < 4; q++) {
                #pragma unroll
                for (int f = 0; f < 4; f++) {
                    int rr = mw*32 + mt*16 + (lane >> 2) + ((f >> 1) << 3);
                    int cc = nwp*32 + (q >> 1)*16 + (q & 1)*8 + (lane & 3)*2 + (f & 1);
                    int i = i0 + rr;
                    int j = j0 + cc;
                    if (j < CC) {
                        float yv = accY[mt][q][f] + mY[rr*TN + cc] + bias[j];
                        float tv = accT[mt][q][f] + mT[rr*TN + cc];
                        d_out[OFF_Y + (size_t)i*CC + j] = yv;
                        g_isda[(size_t)i*CC + j] = yv + 0.5f * ratio * (tv + g_t3[i]);
                    }
                }
            }
        }
    }
}

// ================================================================ loss (exact R12)
__global__ void k_loss(const int* __restrict__ labels, float* __restrict__ d_out) {
    __shared__ float sh[256];
    int i = blockIdx.x;
    const float* row = g_isda + (size_t)i * CC;
    float m = -INFINITY;
    for (int j = threadIdx.x; j < CC; j += 256) m = fmaxf(m, row[j]);
    sh[threadIdx.x] = m;
    __syncthreads();
    for (int s = 128; s > 0; s >>= 1) {
        if (threadIdx.x < s) sh[threadIdx.x] = fmaxf(sh[threadIdx.x], sh[threadIdx.x + s]);
        __syncthreads();
    }
    float mx = sh[0];
    __syncthreads();
    float acc = 0.f;
    for (int j = threadIdx.x; j < CC; j += 256) acc += __expf(row[j] - mx);
    sh[threadIdx.x] = acc;
    __syncthreads();
    for (int s = 128; s > 0; s >>= 1) {
        if (threadIdx.x < s) sh[threadIdx.x] += sh[threadIdx.x + s];
        __syncthreads();
    }
    if (threadIdx.x == 0) {
        float lp = row[labels[i]] - mx - logf(sh[0]);
        atomicAdd(d_out, -lp * (1.0f / (float)NS));
    }
}

// ================================================================ launcher
extern "C" void kernel_launch(void* const* d_in, const int* in_sizes, int n_in,
                              void* d_out, int out_size) {
    const float* features = (const float*)d_in[0];
    const int*   labels   = (const int*)  d_in[1];
    const float* fc_w     = (const float*)d_in[2];
    const float* fc_b     = (const float*)d_in[3];
    const float* ave_in   = (const float*)d_in[4];
    const float* cov_in   = (const float*)d_in[5];
    const float* amt_in   = (const float*)d_in[6];
    const int*   ratio_p  = (const int*)  d_in[7];
    float* out = (float*)d_out;

    cudaFuncSetAttribute(k_gemm_mma, cudaFuncAttributeMaxDynamicSharedMemorySize, GEMM_SMEM);

    k_front<<<FRONT_BLOCKS, 256>>>(features, fc_w, labels, ave_in, cov_in, amt_in, out);
    dim3 grid(CP / TN, NS / TM);          // 16 x 8 = 128 CTAs
    k_gemm_mma<<<grid, 256, GEMM_SMEM>>>(fc_b, ratio_p, out);
    k_loss<<<NS, 256>>>(labels, out);
}

// round 15
// speedup vs baseline: 1.6272x; 1.0303x over previous
#include <cuda_runtime.h>
#include <cuda_bf16.h>
#include <cstdint>
#include <math.h>

// Problem sizes (fixed by setup_inputs)
#define NS 512     // samples
#define AD 2048    // feature dim
#define CC 1000    // classes
#define CP 1024    // classes padded to N-tile multiple

// Output layout: loss(1) | y | new_ave | new_cov | new_amount
#define OFF_Y    1
#define OFF_AVE  (1 + NS*CC)
#define OFF_COV  (OFF_AVE + CC*AD)
#define OFF_AMT  (OFF_COV + CC*AD)

// ---------------------------------------------------------------- scratch
__device__ float g_t3[NS];
__device__ float g_isda[NS*CC];
__device__ __nv_bfloat16 g_fhi[NS*AD], g_flo[NS*AD];     // bf16 split of F
__device__ __nv_bfloat16 g_cvb[NS*AD], g_wcb[NS*AD];     // bf16 cv_n, -2*w_n*cv_n
__device__ __nv_bfloat16 g_whi[CP*AD], g_wlo[CP*AD], g_wsq[CP*AD]; // W split + W^2, padded

// ================================================================ PTX utils
__device__ __forceinline__ uint32_t smem_u32(const void* p) {
    uint32_t a;
    asm("{ .reg .u64 t; cvta.to.shared.u64 t, %1; cvt.u32.u64 %0, t; }" : "=r"(a) : "l"(p));
    return a;
}
#define SWZ(o) ((o) ^ (((o) >> 3) & 0x70))

__device__ __forceinline__ void cp16(uint32_t dst, const void* src) {
    asm volatile("cp.async.cg.shared.global [%0], [%1], 16;" :: "r"(dst), "l"(src) : "memory");
}
#define CP_COMMIT() asm volatile("cp.async.commit_group;" ::: "memory")
template <int N> __device__ __forceinline__ void cp_wait() {
    asm volatile("cp.async.wait_group %0;" :: "n"(N) : "memory");
}
__device__ __forceinline__ void ldsm_x4(uint32_t addr, uint32_t* r) {
    asm volatile("ldmatrix.sync.aligned.m8n8.x4.shared.b16 {%0,%1,%2,%3}, [%4];"
        : "=r"(r[0]), "=r"(r[1]), "=r"(r[2]), "=r"(r[3]) : "r"(addr));
}
__device__ __forceinline__ void mma_bf16(float* d, const uint32_t* a, const uint32_t* b) {
    asm volatile("mma.sync.aligned.m16n8k16.row.col.f32.bf16.bf16.f32 "
        "{%0,%1,%2,%3}, {%4,%5,%6,%7}, {%8,%9}, {%0,%1,%2,%3};"
        : "+f"(d[0]), "+f"(d[1]), "+f"(d[2]), "+f"(d[3])
        : "r"(a[0]), "r"(a[1]), "r"(a[2]), "r"(a[3]), "r"(b[0]), "r"(b[1]));
}

// ================================================================ k_front
#define FCONV_ITEMS (NS*AD/4)          // 262144 float4
#define WCONV_ITEMS (CP*AD/4)          // 524288 float4
#define CONV_TOTAL  (FCONV_ITEMS + WCONV_ITEMS)     // 786432
#define NCONV (CONV_TOTAL / 512)       // 1536 blocks, 2 float4/thread
#define FRONT_BLOCKS (1 + NCONV + CC + NS)

__device__ __forceinline__ void conv_one(int id, const float* __restrict__ F,
                                         const float* __restrict__ W) {
    if (id < FCONV_ITEMS) {
        float4 f = ((const float4*)F)[id];
        float hx = __bfloat162float(__float2bfloat16(f.x));
        float hy = __bfloat162float(__float2bfloat16(f.y));
        float hz = __bfloat162float(__float2bfloat16(f.z));
        float hw = __bfloat162float(__float2bfloat16(f.w));
        __nv_bfloat162* hi = (__nv_bfloat162*)g_fhi;
        __nv_bfloat162* lo = (__nv_bfloat162*)g_flo;
        hi[2*id+0] = __floats2bfloat162_rn(hx, hy);
        hi[2*id+1] = __floats2bfloat162_rn(hz, hw);
        lo[2*id+0] = __floats2bfloat162_rn(f.x - hx, f.y - hy);
        lo[2*id+1] = __floats2bfloat162_rn(f.z - hz, f.w - hw);
    } else {
        int v = id - FCONV_ITEMS;
        int row = (v*4) / AD;
        float4 f = (row < CC) ? ((const float4*)W)[v] : make_float4(0.f, 0.f, 0.f, 0.f);
        float hx = __bfloat162float(__float2bfloat16(f.x));
        float hy = __bfloat162float(__float2bfloat16(f.y));
        float hz = __bfloat162float(__float2bfloat16(f.z));
        float hw = __bfloat162float(__float2bfloat16(f.w));
        __nv_bfloat162* hi = (__nv_bfloat162*)g_whi;
        __nv_bfloat162* lo = (__nv_bfloat162*)g_wlo;
        __nv_bfloat162* sq = (__nv_bfloat162*)g_wsq;
        hi[2*v+0] = __floats2bfloat162_rn(hx, hy);
        hi[2*v+1] = __floats2bfloat162_rn(hz, hw);
        lo[2*v+0] = __floats2bfloat162_rn(f.x - hx, f.y - hy);
        lo[2*v+1] = __floats2bfloat162_rn(f.z - hz, f.w - hw);
        sq[2*v+0] = __floats2bfloat162_rn(f.x*f.x, f.y*f.y);
        sq[2*v+1] = __floats2bfloat162_rn(f.z*f.z, f.w*f.w);
    }
}

__device__ __forceinline__ int build_list(const int* slab, int c, int* list,
                                          int* warp_base, int t) {
    int lane = t & 31, w = t >> 5;
    int p0 = 2*t, p1 = 2*t + 1;
    bool m0 = (slab[p0] == c), m1 = (slab[p1] == c);
    unsigned b0 = __ballot_sync(0xffffffffu, m0);
    unsigned b1 = __ballot_sync(0xffffffffu, m1);
    unsigned lt = (1u << lane) - 1u;
    int below = __popc(b0 & lt) + __popc(b1 & lt);
    int wtot = __popc(b0) + __popc(b1);
    if (lane == 0) warp_base[w] = wtot;
    __syncthreads();
    if (t == 0) {
        int run = 0;
        #pragma unroll
        for (int x = 0; x < 8; x++) { int v = warp_base[x]; warp_base[x] = run; run += v; }
        warp_base[8] = run;
    }
    __syncthreads();
    int base = warp_base[w] + below;
    if (m0) list[base] = p0;
    if (m1) list[base + (m0 ? 1 : 0)] = p1;
    __syncthreads();
    return warp_base[8];
}

__device__ __forceinline__ void class_stats_list(
    const float* __restrict__ F, const int* __restrict__ list, int cnt,
    float inv, int v, float4& mean, float4& q)
{
    float4 s = make_float4(0.f, 0.f, 0.f, 0.f);
    for (int p = 0; p < cnt; p++) {
        const float4* fr = (const float4*)(F + (size_t)list[p] * AD);
        float4 x = fr[v];
        s.x += x.x; s.y += x.y; s.z += x.z; s.w += x.w;
    }
    mean = make_float4(s.x*inv, s.y*inv, s.z*inv, s.w*inv);
    q = make_float4(0.f, 0.f, 0.f, 0.f);
    for (int p = 0; p < cnt; p++) {
        const float4* fr = (const float4*)(F + (size_t)list[p] * AD);
        float4 x = fr[v];
        float dx = x.x-mean.x, dy = x.y-mean.y, dz = x.z-mean.z, dw = x.w-mean.w;
        q.x += dx*dx; q.y += dy*dy; q.z += dz*dz; q.w += dw*dw;
    }
}

__global__ __launch_bounds__(256) void k_front(
    const float* __restrict__ F, const float* __restrict__ W,
    const int* __restrict__ labels,
    const float* __restrict__ ave_in, const float* __restrict__ cov_in,
    const float* __restrict__ amt_in, float* __restrict__ d_out)
{
    int t = threadIdx.x;
    int bx = blockIdx.x;

    if (bx == 0) {
        if (t == 0) d_out[0] = 0.f;
        return;
    }
    bx -= 1;

    if (bx < NCONV) {
        int id0 = bx * 512 + t;
        conv_one(id0, F, W);
        conv_one(id0 + 256, F, W);
        return;
    }
    bx -= NCONV;

    __shared__ int slab[NS];
    __shared__ int list[NS];
    __shared__ int wb[9];
    slab[t] = labels[t];
    slab[t + 256] = labels[t + 256];
    __syncthreads();

    bool is_fin = (bx < CC);
    int i_samp = -1, c;
    if (is_fin) c = bx;
    else { i_samp = bx - CC; c = slab[i_samp]; }

    int cnt = build_list(slab, c, list, wb, t);

    float fcnt = (float)cnt;
    float amt = amt_in[c];
    float dsum = fcnt + amt;
    float w = (dsum > 0.f) ? (fcnt / dsum) : 0.f;
    float omw = 1.f - w;
    size_t base = (size_t)c * AD;
    const float4* av4 = (const float4*)(ave_in + base);
    const float4* cv4 = (const float4*)(cov_in + base);

    if (is_fin) {
        if (t == 0) d_out[OFF_AMT + c] = amt + fcnt;
        if (cnt == 0) {
            #pragma unroll
            for (int h = 0; h < 2; h++) {
                int v = t + h*256;
                float4 a = av4[v];
                float4 cvv = cv4[v];
                long o = base + 4l*v;
                d_out[OFF_AVE + o + 0] = a.x; d_out[OFF_AVE + o + 1] = a.y;
                d_out[OFF_AVE + o + 2] = a.z; d_out[OFF_AVE + o + 3] = a.w;
                d_out[OFF_COV + o + 0] = cvv.x; d_out[OFF_COV + o + 1] = cvv.y;
                d_out[OFF_COV + o + 2] = cvv.z; d_out[OFF_COV + o + 3] = cvv.w;
            }
            return;
        }
        float inv = 1.f / fcnt;
        #pragma unroll
        for (int h = 0; h < 2; h++) {
            int v = t + h*256;
            float4 mean, q;
            class_stats_list(F, list, cnt, inv, v, mean, q);
            float4 a = av4[v];
            float4 c0 = cv4[v];
            float ww = w * omw;
            float d0 = a.x - mean.x, d1 = a.y - mean.y, d2 = a.z - mean.z, d3 = a.w - mean.w;
            long o = base + 4l*v;
            d_out[OFF_AVE + o + 0] = a.x*omw + mean.x*w;
            d_out[OFF_AVE + o + 1] = a.y*omw + mean.y*w;
            d_out[OFF_AVE + o + 2] = a.z*omw + mean.z*w;
            d_out[OFF_AVE + o + 3] = a.w*omw + mean.w*w;
            d_out[OFF_COV + o + 0] = c0.x*omw + q.x*inv*w + ww*d0*d0;
            d_out[OFF_COV + o + 1] = c0.y*omw + q.y*inv*w + ww*d1*d1;
            d_out[OFF_COV + o + 2] = c0.z*omw + q.z*inv*w + ww*d2*d2;
            d_out[OFF_COV + o + 3] = c0.w*omw + q.w*inv*w + ww*d3*d3;
        }
    } else {
        __shared__ float sh[256];
        float inv = 1.f / fcnt;
        const float4* wr = (const float4*)(W + base);
        __nv_bfloat162* cvd = (__nv_bfloat162*)(g_cvb + (size_t)i_samp * AD);
        __nv_bfloat162* wcd = (__nv_bfloat162*)(g_wcb + (size_t)i_samp * AD);
        float acc = 0.f;
        #pragma unroll
        for (int h = 0; h < 2; h++) {
            int v = t + h*256;
            float4 mean, q;
            class_stats_list(F, list, cnt, inv, v, mean, q);
            float4 a = av4[v];
            float4 c0 = cv4[v];
            float ww = w * omw;
            float d0 = a.x - mean.x, d1 = a.y - mean.y, d2 = a.z - mean.z, d3 = a.w - mean.w;
            float4 nc;
            nc.x = c0.x*omw + q.x*inv*w + ww*d0*d0;
            nc.y = c0.y*omw + q.y*inv*w + ww*d1*d1;
            nc.z = c0.z*omw + q.z*inv*w + ww*d2*d2;
            nc.w = c0.w*omw + q.w*inv*w + ww*d3*d3;
            float4 wf = wr[v];
            cvd[2*v+0] = __floats2bfloat162_rn(nc.x, nc.y);
            cvd[2*v+1] = __floats2bfloat162_rn(nc.z, nc.w);
            wcd[2*v+0] = __floats2bfloat162_rn(-2.f*wf.x*nc.x, -2.f*wf.y*nc.y);
            wcd[2*v+1] = __floats2bfloat162_rn(-2.f*wf.z*nc.z, -2.f*wf.w*nc.w);
            acc += wf.x*wf.x*nc.x + wf.y*wf.y*nc.y + wf.z*wf.z*nc.z + wf.w*wf.w*nc.w;
        }
        sh[t] = acc;
        __syncthreads();
        for (int s = 128; s > 0; s >>= 1) {
            if (t < s) sh[t] += sh[t + s];
            __syncthreads();
        }
        if (t == 0) g_t3[i_samp] = sh[0];
    }
}

// ================================================================ HMMA GEMM (exact R14)
#define TM 64
#define TN 64
#define KC 64
#define KITERS (AD/KC)              // 32
#define MAT_BYTES (64*128)          // 8192 per matrix per stage
#define STAGE_BYTES (7*MAT_BYTES)   // 57344
#define GEMM_SMEM (2*STAGE_BYTES)   // 114688

__device__ __forceinline__ void load_stage(uint32_t stg, int k0, int i0, int j0, int tid) {
    const __nv_bfloat16* As[4] = {g_fhi, g_flo, g_cvb, g_wcb};
    const __nv_bfloat16* Bs[3] = {g_whi, g_wlo, g_wsq};
    #pragma unroll
    for (int q = 0; q < 14; q++) {
        int id = tid + q*256;
        int m = (id >> 9) & 7;
        int idx = id & 511;
        int r = idx >> 3, c = idx & 7;
        if (id < 2048) {
            const __nv_bfloat16* src = As[m] + (size_t)(i0 + r)*AD + k0 + c*8;
            cp16(stg + m*MAT_BYTES + SWZ(r*128 + c*16), src);
        } else {
            m = (id - 2048) >> 9;
            const __nv_bfloat16* src = Bs[m] + (size_t)(j0 + r)*AD + k0 + c*8;
            cp16(stg + (4+m)*MAT_BYTES + SWZ(r*128 + c*16), src);
        }
    }
}

__global__ __launch_bounds__(256, 1) void k_gemm_mma(
    const float* __restrict__ bias, const int* __restrict__ ratio_bits,
    float* __restrict__ d_out)
{
    extern __shared__ char smem[];
    uint32_t sb = smem_u32(smem);
    int tid = threadIdx.x, wid = tid >> 5, lane = tid & 31;
    int mw = wid & 1, nwp = (wid >> 1) & 1, kw = wid >> 2;   // 2M x 2N x 2Ksl
    int i0 = blockIdx.y * TM, j0 = blockIdx.x * TN;

    float accY[2][4][4] = {};   // [mt][bt*2+nt8][frag]
    float accT[2][4][4] = {};

    uint32_t stg0 = sb, stg1 = sb + STAGE_BYTES;
    load_stage(stg0, 0,  i0, j0, tid); CP_COMMIT();
    load_stage(stg1, KC, i0, j0, tid); CP_COMMIT();

    for (int it = 0; it < KITERS; ++it) {
        uint32_t stg = (it & 1) ? stg1 : stg0;
        if (it == KITERS - 1) cp_wait<0>(); else cp_wait<1>();
        __syncthreads();

        #pragma unroll
        for (int s = 0; s < 2; s++) {
            int ks = kw*2 + s;
            uint32_t a[4][2][4];
            int arow = mw*32 + (lane & 15);
            int akb  = ks*32 + ((lane >> 4) << 4);
            #pragma unroll
            for (int m = 0; m < 4; m++) {
                #pragma unroll
                for (int mt = 0; mt < 2; mt++) {
                    uint32_t addr = stg + m*MAT_BYTES + SWZ((arow + mt*16)*128 + akb);
                    ldsm_x4(addr, a[m][mt]);
                }
            }
            uint32_t b[3][2][4];
            int bkb = ks*32 + (((lane >> 3) & 1) << 4);
            #pragma unroll
            for (int m = 0; m < 3; m++) {
                #pragma unroll
                for (int bt = 0; bt < 2; bt++) {
                    int brow = nwp*32 + bt*16 + ((lane >> 4) << 3) + (lane & 7);
                    uint32_t addr = stg + (4+m)*MAT_BYTES + SWZ(brow*128 + bkb);
                    ldsm_x4(addr, b[m][bt]);
                }
            }
            #pragma unroll
            for (int mt = 0; mt < 2; mt++) {
                #pragma unroll
                for (int bt = 0; bt < 2; bt++) {
                    #pragma unroll
                    for (int n8 = 0; n8 < 2; n8++) {
                        int q = bt*2 + n8;
                        const uint32_t* bw = &b[0][bt][n8*2];
                        const uint32_t* bl = &b[1][bt][n8*2];
                        const uint32_t* bs = &b[2][bt][n8*2];
                        mma_bf16(accY[mt][q], a[0][mt], bw);
                        mma_bf16(accY[mt][q], a[0][mt], bl);
                        mma_bf16(accY[mt][q], a[1][mt], bw);
                        mma_bf16(accT[mt][q], a[2][mt], bs);
                        mma_bf16(accT[mt][q], a[3][mt], bw);
                    }
                }
            }
        }
        __syncthreads();
        if (it + 2 < KITERS) {
            load_stage(stg, (it + 2)*KC, i0, j0, tid);
            CP_COMMIT();
        }
    }

    __syncthreads();
    float* mY = (float*)smem;
    float* mT = mY + TM*TN;
    if (kw == 1) {
        #pragma unroll
        for (int mt = 0; mt < 2; mt++) {
            #pragma unroll
            for (int q = 0; q < 4; q++) {
                #pragma unroll
                for (int f = 0; f < 4; f++) {
                    int rr = mw*32 + mt*16 + (lane >> 2) + ((f >> 1) << 3);
                    int cc = nwp*32 + (q >> 1)*16 + (q & 1)*8 + (lane & 3)*2 + (f & 1);
                    mY[rr*TN + cc] = accY[mt][q][f];
                    mT[rr*TN + cc] = accT[mt][q][f];
                }
            }
        }
    }
    __syncthreads();

    if (kw == 0) {
        int bits = *ratio_bits;
        float ratio = (bits & 0x7f800000) ? __int_as_float(bits) : (float)bits;
        #pragma unroll
        for (int mt = 0; mt < 2; mt++) {
            #pragma unroll
            for (int q = 0; q < 4; q++) {
                #pragma unroll
                for (int f = 0; f < 4; f++) {
                    int rr = mw*32 + mt*16 + (lane >> 2) + ((f >> 1) << 3);
                    int cc = nwp*32 + (q >> 1)*16 + (q & 1)*8 + (lane & 3)*2 + (f & 1);
                    int i = i0 + rr;
                    int j = j0 + cc;
                    if (j < CC) {
                        float yv = accY[mt][q][f] + mY[rr*TN + cc] + bias[j];
                        float tv = accT[mt][q][f] + mT[rr*TN + cc];
                        d_out[OFF_Y + (size_t)i*CC + j] = yv;
                        g_isda[(size_t)i*CC + j] = yv + 0.5f * ratio * (tv + g_t3[i]);
                    }
                }
            }
        }
    }
}

// ================================================================ loss: one warp per row, registers only
__global__ __launch_bounds__(128) void k_loss(const int* __restrict__ labels,
                                              float* __restrict__ d_out) {
    int w = threadIdx.x >> 5, lane = threadIdx.x & 31;
    int i = blockIdx.x * 4 + w;
    const float4* row4 = (const float4*)(g_isda + (size_t)i * CC);   // 250 float4

    float4 v[8];
    #pragma unroll
    for (int c = 0; c < 8; c++) {
        int idx = lane + c*32;
        v[c] = (idx < 250) ? row4[idx] : make_float4(-INFINITY, -INFINITY, -INFINITY, -INFINITY);
    }
    float m = -INFINITY;
    #pragma unroll
    for (int c = 0; c < 8; c++)
        m = fmaxf(m, fmaxf(fmaxf(v[c].x, v[c].y), fmaxf(v[c].z, v[c].w)));
    #pragma unroll
    for (int off = 16; off > 0; off >>= 1)
        m = fmaxf(m, __shfl_xor_sync(0xffffffffu, m, off));

    float s = 0.f;
    #pragma unroll
    for (int c = 0; c < 8; c++) {
        if (lane + c*32 < 250) {
            s += __expf(v[c].x - m) + __expf(v[c].y - m)
               + __expf(v[c].z - m) + __expf(v[c].w - m);
        }
    }
    #pragma unroll
    for (int off = 16; off > 0; off >>= 1)
        s += __shfl_xor_sync(0xffffffffu, s, off);

    if (lane == 0) {
        float lv = g_isda[(size_t)i * CC + labels[i]];
        float lp = lv - m - logf(s);
        atomicAdd(d_out, -lp * (1.0f / (float)NS));
    }
}

// ================================================================ launcher
extern "C" void kernel_launch(void* const* d_in, const int* in_sizes, int n_in,
                              void* d_out, int out_size) {
    const float* features = (const float*)d_in[0];
    const int*   labels   = (const int*)  d_in[1];
    const float* fc_w     = (const float*)d_in[2];
    const float* fc_b     = (const float*)d_in[3];
    const float* ave_in   = (const float*)d_in[4];
    const float* cov_in   = (const float*)d_in[5];
    const float* amt_in   = (const float*)d_in[6];
    const int*   ratio_p  = (const int*)  d_in[7];
    float* out = (float*)d_out;

    cudaFuncSetAttribute(k_gemm_mma, cudaFuncAttributeMaxDynamicSharedMemorySize, GEMM_SMEM);

    k_front<<<FRONT_BLOCKS, 256>>>(features, fc_w, labels, ave_in, cov_in, amt_in, out);
    dim3 grid(CP / TN, NS / TM);          // 16 x 8 = 128 CTAs
    k_gemm_mma<<<grid, 256, GEMM_SMEM>>>(fc_b, ratio_p, out);
    k_loss<<<NS/4, 128>>>(labels, out);
}